// round 1
// baseline (speedup 1.0000x reference)
#include <cuda_runtime.h>
#include <math.h>

// Problem constants
#define NB1 8192
#define NB2 8192
#define ND  128

// Tiling
#define BM 128          // rows of desc1 per block
#define BN 64           // cols of desc2 per chunk
#define SPLIT 32        // column splits across blockIdx.y
#define COLS_PER_BLOCK (NB2 / SPLIT)   // 256
#define A_PITCH 132     // padded pitch for transposed A tile (16B-aligned, conflict-reduced)
#define B_PITCH 68      // padded pitch for transposed B tile

#define SMEM_BYTES ((ND * A_PITCH + ND * B_PITCH) * 4)   // 102400 bytes

// Scratch (no allocations allowed -> device globals)
__device__ float g_n1[NB1];
__device__ float g_n2[NB2];
__device__ float g_pval[NB1 * SPLIT];
__device__ int   g_pidx[NB1 * SPLIT];

// ---------------------------------------------------------------------------
// Kernel 1: squared norms of every row of desc1 and desc2 (warp per row)
// ---------------------------------------------------------------------------
__global__ void norms_kernel(const float* __restrict__ d1,
                             const float* __restrict__ d2) {
    int warp = (blockIdx.x * blockDim.x + threadIdx.x) >> 5;
    int lane = threadIdx.x & 31;
    if (warp >= NB1 + NB2) return;
    const float* src = (warp < NB1) ? (d1 + (size_t)warp * ND)
                                    : (d2 + (size_t)(warp - NB1) * ND);
    float4 v = ((const float4*)src)[lane];      // 32 lanes * 4 = 128 = ND
    float s = v.x * v.x + v.y * v.y + v.z * v.z + v.w * v.w;
    #pragma unroll
    for (int o = 16; o; o >>= 1) s += __shfl_xor_sync(0xffffffffu, s, o);
    if (lane == 0) {
        if (warp < NB1) g_n1[warp] = s;
        else            g_n2[warp - NB1] = s;
    }
}

// ---------------------------------------------------------------------------
// Kernel 2: fused GEMM + running argmin over (n2[j] - 2 * a_i . b_j)
// Block: 256 threads, computes BM x BN outputs per chunk, 8x4 per thread.
// A and B tiles stored K-major (transposed) in smem so the k-loop uses
// vectorized LDS.128 with broadcast/low-conflict access.
// ---------------------------------------------------------------------------
__global__ __launch_bounds__(256, 2)
void match_kernel(const float* __restrict__ A, const float* __restrict__ Bm) {
    extern __shared__ float smem[];
    float* As = smem;                  // [ND][A_PITCH]
    float* Bs = smem + ND * A_PITCH;   // [ND][B_PITCH]
    __shared__ float n2s[BN];

    const int tid = threadIdx.x;
    const int tx = tid & 15;   // column group: 16 * 4 = 64 cols
    const int ty = tid >> 4;   // row group:    16 * 8 = 128 rows
    const int rowBase = blockIdx.x * BM;
    const int colBase = blockIdx.y * COLS_PER_BLOCK;

    // Load A tile (coalesced global read, transposed store). Once per block.
    #pragma unroll
    for (int i = 0; i < (BM * ND) / 256; i++) {
        int idx = i * 256 + tid;
        int m = idx >> 7;          // / ND
        int k = idx & (ND - 1);
        As[k * A_PITCH + m] = A[(size_t)(rowBase + m) * ND + k];
    }

    float best[8];
    int   bidx[8];
    #pragma unroll
    for (int r = 0; r < 8; r++) { best[r] = 3.4e38f; bidx[r] = 0; }

    for (int c0 = 0; c0 < COLS_PER_BLOCK; c0 += BN) {
        __syncthreads();   // previous-iteration smem reads done (also covers A stores, iter 0)

        // Load B tile transposed (coalesced global read)
        #pragma unroll
        for (int i = 0; i < (BN * ND) / 256; i++) {
            int idx = i * 256 + tid;
            int n = idx >> 7;
            int k = idx & (ND - 1);
            Bs[k * B_PITCH + n] = Bm[(size_t)(colBase + c0 + n) * ND + k];
        }
        if (tid < BN) n2s[tid] = g_n2[colBase + c0 + tid];
        __syncthreads();

        float acc[8][4];
        #pragma unroll
        for (int r = 0; r < 8; r++)
            #pragma unroll
            for (int cc = 0; cc < 4; cc++) acc[r][cc] = 0.0f;

        #pragma unroll 4
        for (int k = 0; k < ND; k++) {
            float4 a0 = *(const float4*)&As[k * A_PITCH + ty * 8];
            float4 a1 = *(const float4*)&As[k * A_PITCH + ty * 8 + 4];
            float4 b  = *(const float4*)&Bs[k * B_PITCH + tx * 4];
            float av[8] = {a0.x, a0.y, a0.z, a0.w, a1.x, a1.y, a1.z, a1.w};
            float bv[4] = {b.x, b.y, b.z, b.w};
            #pragma unroll
            for (int r = 0; r < 8; r++)
                #pragma unroll
                for (int cc = 0; cc < 4; cc++)
                    acc[r][cc] = fmaf(av[r], bv[cc], acc[r][cc]);
        }

        // Epilogue: running min of n2 - 2*dot (n1 added later; constant per row)
        #pragma unroll
        for (int r = 0; r < 8; r++) {
            #pragma unroll
            for (int cc = 0; cc < 4; cc++) {
                float v = n2s[tx * 4 + cc] - 2.0f * acc[r][cc];
                int col = colBase + c0 + tx * 4 + cc;
                if (v < best[r]) { best[r] = v; bidx[r] = col; }  // strict < => first occurrence
            }
        }
    }

    // Cross-thread (tx) reduction via smem (reuse tile storage)
    __syncthreads();
    float* vbuf = smem;                         // BM * 16 floats
    int*   ibuf = (int*)(smem + BM * 16);       // BM * 16 ints
    #pragma unroll
    for (int r = 0; r < 8; r++) {
        vbuf[(ty * 8 + r) * 16 + tx] = best[r];
        ibuf[(ty * 8 + r) * 16 + tx] = bidx[r];
    }
    __syncthreads();
    if (tid < BM) {
        float bv = vbuf[tid * 16];
        int   bi = ibuf[tid * 16];
        #pragma unroll
        for (int j = 1; j < 16; j++) {
            float v = vbuf[tid * 16 + j];
            int  ii = ibuf[tid * 16 + j];
            if (v < bv || (v == bv && ii < bi)) { bv = v; bi = ii; }
        }
        size_t p = (size_t)(rowBase + tid) * SPLIT + blockIdx.y;
        g_pval[p] = bv;
        g_pidx[p] = bi;
    }
}

// ---------------------------------------------------------------------------
// Kernel 3: reduce the SPLIT partials per row, add n1, sqrt, write outputs.
// Output layout: [0, NB1) dists; [NB1, NB1+2*NB1) (i, idx) pairs as floats.
// ---------------------------------------------------------------------------
__global__ void final_kernel(float* __restrict__ out) {
    int i = blockIdx.x * blockDim.x + threadIdx.x;
    if (i >= NB1) return;
    size_t base = (size_t)i * SPLIT;
    float bv = g_pval[base];
    int   bi = g_pidx[base];
    #pragma unroll
    for (int y = 1; y < SPLIT; y++) {
        float v = g_pval[base + y];
        int  ii = g_pidx[base + y];
        if (v < bv || (v == bv && ii < bi)) { bv = v; bi = ii; }
    }
    float dm = g_n1[i] + bv;
    out[i] = sqrtf(fmaxf(dm, 0.0f));
    out[NB1 + 2 * i]     = (float)i;
    out[NB1 + 2 * i + 1] = (float)bi;
}

// ---------------------------------------------------------------------------
extern "C" void kernel_launch(void* const* d_in, const int* in_sizes, int n_in,
                              void* d_out, int out_size) {
    const float* d1 = (const float*)d_in[0];
    const float* d2 = (const float*)d_in[1];
    float* out = (float*)d_out;

    cudaFuncSetAttribute(match_kernel,
                         cudaFuncAttributeMaxDynamicSharedMemorySize, SMEM_BYTES);

    norms_kernel<<<(NB1 + NB2) / 8, 256>>>(d1, d2);
    match_kernel<<<dim3(NB1 / BM, SPLIT), 256, SMEM_BYTES>>>(d1, d2);
    final_kernel<<<NB1 / 256, 256>>>(out);
}

// round 3
// speedup vs baseline: 4.5278x; 4.5278x over previous
#include <cuda_runtime.h>
#include <cuda_fp16.h>
#include <math.h>
#include <stdint.h>

// ---------------- problem constants ----------------
#define NB1 8192
#define NB2 8192
#define ND  128

// ---------------- match tiling ----------------
#define BM 128
#define BN 64
#define SPLITC 16
#define COLS_PER_CTA (NB2 / SPLITC)          // 512
#define TILES (COLS_PER_CTA / BN)            // 8

// smem: A panel 64KB (hi+lo), B double-buffer 2 x 32KB (hi+lo)
#define SMEM_A 0
#define SMEM_B 65536
#define SMEM_BYTES 131072

#define SW128(o) ((o) ^ (((o) >> 3) & 0x70))

// ---------------- scratch globals ----------------
__device__ __align__(16) float  g_n1[NB1];
__device__ __align__(16) float  g_n2[NB2];
__device__ __align__(16) __half g_Ah[NB1 * ND];
__device__ __align__(16) __half g_Al[NB1 * ND];
__device__ __align__(16) __half g_Bh[NB2 * ND];
__device__ __align__(16) __half g_Bl[NB2 * ND];
__device__ float g_pval[NB1 * SPLITC];
__device__ int   g_pidx[NB1 * SPLITC];

// ---------------- PTX helpers (portable sm_80-level only) ----------------
__device__ __forceinline__ uint32_t smem_u32(const void* p) {
    uint32_t a;
    asm("{ .reg .u64 t; cvta.to.shared.u64 t, %1; cvt.u32.u64 %0, t; }" : "=r"(a) : "l"(p));
    return a;
}
#define CP_ASYNC16(dst, src) \
    asm volatile("cp.async.cg.shared.global [%0], [%1], 16;" :: "r"(dst), "l"(src) : "memory")
#define CP_COMMIT() asm volatile("cp.async.commit_group;" ::: "memory")
#define CP_WAIT1()  asm volatile("cp.async.wait_group 1;" ::: "memory")
#define CP_WAIT0()  asm volatile("cp.async.wait_group 0;" ::: "memory")

#define LDMATRIX_X4(r0, r1, r2, r3, addr) \
    asm volatile("ldmatrix.sync.aligned.m8n8.x4.shared.b16 {%0,%1,%2,%3}, [%4];" \
        : "=r"(r0), "=r"(r1), "=r"(r2), "=r"(r3) : "r"(addr))

#define MMA16816(acc, a, b0v, b1v) \
    asm volatile("mma.sync.aligned.m16n8k16.row.col.f32.f16.f16.f32 " \
        "{%0,%1,%2,%3}, {%4,%5,%6,%7}, {%8,%9}, {%0,%1,%2,%3};" \
        : "+f"((acc)[0]), "+f"((acc)[1]), "+f"((acc)[2]), "+f"((acc)[3]) \
        : "r"((a)[0]), "r"((a)[1]), "r"((a)[2]), "r"((a)[3]), "r"(b0v), "r"(b1v))

// ---------------------------------------------------------------------------
// Kernel 0: squared norms (warp per row)
// ---------------------------------------------------------------------------
__global__ void norms_kernel(const float* __restrict__ d1,
                             const float* __restrict__ d2) {
    int warp = (blockIdx.x * blockDim.x + threadIdx.x) >> 5;
    int lane = threadIdx.x & 31;
    if (warp >= NB1 + NB2) return;
    const float* src = (warp < NB1) ? (d1 + (size_t)warp * ND)
                                    : (d2 + (size_t)(warp - NB1) * ND);
    float4 v = ((const float4*)src)[lane];
    float s = v.x * v.x + v.y * v.y + v.z * v.z + v.w * v.w;
    #pragma unroll
    for (int o = 16; o; o >>= 1) s += __shfl_xor_sync(0xffffffffu, s, o);
    if (lane == 0) {
        if (warp < NB1) g_n1[warp] = s;
        else            g_n2[warp - NB1] = s;
    }
}

// ---------------------------------------------------------------------------
// Kernel 1: fp16 Dekker split: hi = fp16(a), lo = fp16(a - hi)
// ---------------------------------------------------------------------------
__global__ void conv_kernel(const float* __restrict__ d1,
                            const float* __restrict__ d2) {
    int i = blockIdx.x * blockDim.x + threadIdx.x;   // float4 index
    const int nA = NB1 * ND / 4;
    bool isB = (i >= nA);
    int j = isB ? i - nA : i;
    const float4 v = ((const float4*)(isB ? d2 : d1))[j];
    __half2 h01, h23, l01, l23;
    {
        __half hx = __float2half_rn(v.x), hy = __float2half_rn(v.y);
        __half hz = __float2half_rn(v.z), hw = __float2half_rn(v.w);
        h01 = __halves2half2(hx, hy);
        h23 = __halves2half2(hz, hw);
        l01 = __halves2half2(__float2half_rn(v.x - __half2float(hx)),
                             __float2half_rn(v.y - __half2float(hy)));
        l23 = __halves2half2(__float2half_rn(v.z - __half2float(hz)),
                             __float2half_rn(v.w - __half2float(hw)));
    }
    uint2 hp = make_uint2(*(uint32_t*)&h01, *(uint32_t*)&h23);
    uint2 lp = make_uint2(*(uint32_t*)&l01, *(uint32_t*)&l23);
    ((uint2*)(isB ? g_Bh : g_Ah))[j] = hp;
    ((uint2*)(isB ? g_Bl : g_Al))[j] = lp;
}

// ---------------------------------------------------------------------------
// smem loaders (SW128-swizzled K-major tiles, 16B granules via cp.async)
// A: [half][kchunk 2][128 rows][128B]   B stage: [half][kchunk 2][64 rows][128B]
// ---------------------------------------------------------------------------
__device__ __forceinline__ void load_a_panel(uint32_t dstbase, int row0, int tid) {
    #pragma unroll
    for (int g = 0; g < 16; g++) {
        int idx = g * 256 + tid;            // 4096 granules
        int half_ = idx >> 11;
        int rem   = idx & 2047;
        int chunk = rem >> 10;
        int rem2  = rem & 1023;
        int row   = rem2 >> 3;
        int gi    = rem2 & 7;
        const __half* src = (half_ ? g_Al : g_Ah) +
                            (size_t)(row0 + row) * ND + chunk * 64 + gi * 8;
        uint32_t dst = dstbase + half_ * 32768 + chunk * 16384 +
                       SW128(row * 128 + gi * 16);
        CP_ASYNC16(dst, src);
    }
}
__device__ __forceinline__ void load_b_stage(uint32_t dstbase, int col0, int tid) {
    #pragma unroll
    for (int g = 0; g < 8; g++) {
        int idx = g * 256 + tid;            // 2048 granules
        int half_ = idx >> 10;
        int rem   = idx & 1023;
        int chunk = rem >> 9;
        int rem2  = rem & 511;
        int row   = rem2 >> 3;
        int gi    = rem2 & 7;
        const __half* src = (half_ ? g_Bl : g_Bh) +
                            (size_t)(col0 + row) * ND + chunk * 64 + gi * 8;
        uint32_t dst = dstbase + half_ * 16384 + chunk * 8192 +
                       SW128(row * 128 + gi * 16);
        CP_ASYNC16(dst, src);
    }
}

// ---------------------------------------------------------------------------
// Kernel 2: mma.sync fp16x3 GEMM + fused argmin
// 256 threads = 8 warps (4 row x 2 col); warp tile 32x32.
// ---------------------------------------------------------------------------
__global__ void __launch_bounds__(256, 1)
match_kernel() {
    extern __shared__ char smem[];
    const uint32_t sbase = smem_u32(smem);
    const int tid  = threadIdx.x;
    const int lane = tid & 31;
    const int warp = tid >> 5;
    const int wrow = (warp >> 1) * 32;
    const int wcol = (warp & 1) * 32;
    const int rowBase = blockIdx.x * BM;
    const int split   = blockIdx.y;
    const int colBase = split * COLS_PER_CTA;

    // per-lane ldmatrix geometry
    const int a_rl   = lane & 15;           // local row within m16
    const int a_koff = (lane >> 4) * 8;     // k granule select
    const int b_nl   = (lane & 7) + (lane >> 4) * 8;  // local n within n16
    const int b_koff = ((lane >> 3) & 1) * 8;

    // ---- prologue: A panel + first two B stages ----
    load_a_panel(sbase + SMEM_A, rowBase, tid);
    load_b_stage(sbase + SMEM_B + 0 * 32768, colBase + 0 * BN, tid);
    CP_COMMIT();                                    // G0 = A + B0
    load_b_stage(sbase + SMEM_B + 1 * 32768, colBase + 1 * BN, tid);
    CP_COMMIT();                                    // G1 = B1

    float best[4];
    int   bidx[4];
    #pragma unroll
    for (int s = 0; s < 4; s++) { best[s] = 3.4e38f; bidx[s] = 0; }

    for (int i = 0; i < TILES; i++) {
        if (i < TILES - 1) CP_WAIT1(); else CP_WAIT0();
        __syncthreads();

        const int stage = i & 1;
        float acc[2][4][4];
        #pragma unroll
        for (int m = 0; m < 2; m++)
            #pragma unroll
            for (int n = 0; n < 4; n++)
                #pragma unroll
                for (int c = 0; c < 4; c++) acc[m][n][c] = 0.0f;

        // 3 passes: (Ah,Bh), (Ah,Bl), (Al,Bh)
        #pragma unroll
        for (int p = 0; p < 3; p++) {
            const uint32_t abase = sbase + SMEM_A + ((p == 2) ? 32768 : 0);
            const uint32_t bbase = sbase + SMEM_B + stage * 32768 +
                                   ((p == 1) ? 16384 : 0);
            #pragma unroll
            for (int ks = 0; ks < 8; ks++) {
                uint32_t aF[2][4], bF[2][4];
                #pragma unroll
                for (int m = 0; m < 2; m++) {
                    int row = wrow + m * 16 + a_rl;
                    int kb  = ks * 16 + a_koff;
                    uint32_t addr = abase + (kb >> 6) * 16384 + row * 128 +
                                    (((kb & 63) * 2) ^ ((row & 7) << 4));
                    LDMATRIX_X4(aF[m][0], aF[m][1], aF[m][2], aF[m][3], addr);
                }
                #pragma unroll
                for (int pr = 0; pr < 2; pr++) {
                    int nrow = wcol + pr * 16 + b_nl;
                    int kb   = ks * 16 + b_koff;
                    uint32_t addr = bbase + (kb >> 6) * 8192 + nrow * 128 +
                                    (((kb & 63) * 2) ^ ((nrow & 7) << 4));
                    LDMATRIX_X4(bF[pr][0], bF[pr][1], bF[pr][2], bF[pr][3], addr);
                }
                #pragma unroll
                for (int m = 0; m < 2; m++) {
                    MMA16816(acc[m][0], aF[m], bF[0][0], bF[0][1]);
                    MMA16816(acc[m][1], aF[m], bF[0][2], bF[0][3]);
                    MMA16816(acc[m][2], aF[m], bF[1][0], bF[1][1]);
                    MMA16816(acc[m][3], aF[m], bF[1][2], bF[1][3]);
                }
            }
        }

        // ---- fused argmin epilogue ----
        const int c0 = colBase + i * BN + wcol;
        float n2v[8];
        #pragma unroll
        for (int n = 0; n < 4; n++) {
            n2v[n * 2]     = g_n2[c0 + n * 8 + (lane & 3) * 2];
            n2v[n * 2 + 1] = g_n2[c0 + n * 8 + (lane & 3) * 2 + 1];
        }
        #pragma unroll
        for (int m = 0; m < 2; m++)
            #pragma unroll
            for (int n = 0; n < 4; n++)
                #pragma unroll
                for (int c = 0; c < 4; c++) {
                    float v = n2v[n * 2 + (c & 1)] - 2.0f * acc[m][n][c];
                    int col = c0 + n * 8 + (lane & 3) * 2 + (c & 1);
                    int s = m * 2 + (c >> 1);
                    if (v < best[s]) { best[s] = v; bidx[s] = col; }
                }

        __syncthreads();
        if (i + 2 < TILES) {
            load_b_stage(sbase + SMEM_B + stage * 32768, colBase + (i + 2) * BN, tid);
            CP_COMMIT();
        }
    }

    // ---- reduction: quad lanes share rows -> shfl, then 2 col-warps via smem
    float* red_v = (float*)smem;                 // 256 floats
    int*   red_i = (int*)(smem + 1024);          // 256 ints
    __syncthreads();
    #pragma unroll
    for (int s = 0; s < 4; s++) {
        float bv = best[s];
        int   bi = bidx[s];
        #pragma unroll
        for (int off = 1; off <= 2; off <<= 1) {
            float ov = __shfl_xor_sync(0xffffffffu, bv, off);
            int   oi = __shfl_xor_sync(0xffffffffu, bi, off);
            if (ov < bv || (ov == bv && oi < bi)) { bv = ov; bi = oi; }
        }
        if ((lane & 3) == 0) {
            int row = wrow + (s >> 1) * 16 + (s & 1) * 8 + (lane >> 2);
            red_v[row * 2 + (warp & 1)] = bv;
            red_i[row * 2 + (warp & 1)] = bi;
        }
    }
    __syncthreads();
    if (tid < BM) {
        float bv = red_v[tid * 2];
        int   bi = red_i[tid * 2];
        float ov = red_v[tid * 2 + 1];
        int   oi = red_i[tid * 2 + 1];
        if (ov < bv || (ov == bv && oi < bi)) { bv = ov; bi = oi; }
        g_pval[(rowBase + tid) * SPLITC + split] = bv;
        g_pidx[(rowBase + tid) * SPLITC + split] = bi;
    }
}

// ---------------------------------------------------------------------------
// Kernel 3: reduce SPLITC partials, add n1, sqrt, write outputs
// ---------------------------------------------------------------------------
__global__ void final_kernel(float* __restrict__ out) {
    int i = blockIdx.x * blockDim.x + threadIdx.x;
    if (i >= NB1) return;
    float bv = g_pval[i * SPLITC];
    int   bi = g_pidx[i * SPLITC];
    #pragma unroll
    for (int y = 1; y < SPLITC; y++) {
        float v = g_pval[i * SPLITC + y];
        int  ii = g_pidx[i * SPLITC + y];
        if (v < bv || (v == bv && ii < bi)) { bv = v; bi = ii; }
    }
    float dm = g_n1[i] + bv;
    out[i] = sqrtf(fmaxf(dm, 0.0f));
    out[NB1 + 2 * i]     = (float)i;
    out[NB1 + 2 * i + 1] = (float)bi;
}

// ---------------------------------------------------------------------------
extern "C" void kernel_launch(void* const* d_in, const int* in_sizes, int n_in,
                              void* d_out, int out_size) {
    const float* d1 = (const float*)d_in[0];
    const float* d2 = (const float*)d_in[1];
    float* out = (float*)d_out;

    cudaFuncSetAttribute(match_kernel,
                         cudaFuncAttributeMaxDynamicSharedMemorySize, SMEM_BYTES);

    norms_kernel<<<(NB1 + NB2) / 8, 256>>>(d1, d2);
    conv_kernel<<<(2 * NB1 * ND / 4) / 256, 256>>>(d1, d2);
    match_kernel<<<dim3(NB1 / BM, SPLITC), 256, SMEM_BYTES>>>();
    final_kernel<<<NB1 / 256, 256>>>(out);
}

// round 4
// speedup vs baseline: 5.1206x; 1.1309x over previous
#include <cuda_runtime.h>
#include <cuda_fp16.h>
#include <math.h>
#include <stdint.h>

// ---------------- problem constants ----------------
#define NB1 8192
#define NB2 8192
#define ND  128

// ---------------- match tiling ----------------
#define BM 128
#define BN 64
#define SPLITC 16
#define COLS_PER_CTA (NB2 / SPLITC)          // 512
#define TILES (COLS_PER_CTA / BN)            // 8

// smem map: A 64KB | B ring 3 x 32KB | n2 2KB
#define SMEM_A 0
#define SMEM_B 65536
#define BSTAGE 32768
#define SMEM_N2 (SMEM_B + 3 * BSTAGE)        // 163840
#define SMEM_BYTES (SMEM_N2 + 2048)          // 165888

#define SW128(o) ((o) ^ (((o) >> 3) & 0x70))

// ---------------- scratch globals ----------------
__device__ __align__(16) float  g_n1[NB1];
__device__ __align__(16) float  g_n2[NB2];
__device__ __align__(16) __half g_Ah[NB1 * ND];
__device__ __align__(16) __half g_Al[NB1 * ND];
__device__ __align__(16) __half g_Bh[NB2 * ND];
__device__ __align__(16) __half g_Bl[NB2 * ND];
__device__ float g_pval[NB1 * SPLITC];
__device__ int   g_pidx[NB1 * SPLITC];

// ---------------- PTX helpers (portable sm_80-level only) ----------------
__device__ __forceinline__ uint32_t smem_u32(const void* p) {
    uint32_t a;
    asm("{ .reg .u64 t; cvta.to.shared.u64 t, %1; cvt.u32.u64 %0, t; }" : "=r"(a) : "l"(p));
    return a;
}
#define CP_ASYNC16(dst, src) \
    asm volatile("cp.async.cg.shared.global [%0], [%1], 16;" :: "r"(dst), "l"(src) : "memory")
#define CP_COMMIT() asm volatile("cp.async.commit_group;" ::: "memory")
#define CP_WAIT1()  asm volatile("cp.async.wait_group 1;" ::: "memory")

#define LDMATRIX_X4(r0, r1, r2, r3, addr) \
    asm volatile("ldmatrix.sync.aligned.m8n8.x4.shared.b16 {%0,%1,%2,%3}, [%4];" \
        : "=r"(r0), "=r"(r1), "=r"(r2), "=r"(r3) : "r"(addr))

#define MMA16816(acc, a, b0v, b1v) \
    asm volatile("mma.sync.aligned.m16n8k16.row.col.f32.f16.f16.f32 " \
        "{%0,%1,%2,%3}, {%4,%5,%6,%7}, {%8,%9}, {%0,%1,%2,%3};" \
        : "+f"((acc)[0]), "+f"((acc)[1]), "+f"((acc)[2]), "+f"((acc)[3]) \
        : "r"((a)[0]), "r"((a)[1]), "r"((a)[2]), "r"((a)[3]), "r"(b0v), "r"(b1v))

// ---------------------------------------------------------------------------
// Kernel 0 (fused): fp16 Dekker split + squared norms. One warp per row.
// ---------------------------------------------------------------------------
__global__ void prep_kernel(const float* __restrict__ d1,
                            const float* __restrict__ d2) {
    int warp = (blockIdx.x * blockDim.x + threadIdx.x) >> 5;
    int lane = threadIdx.x & 31;
    if (warp >= NB1 + NB2) return;
    bool isB = (warp >= NB1);
    int row = isB ? warp - NB1 : warp;
    const float* src = (isB ? d2 : d1) + (size_t)row * ND;
    float4 v = ((const float4*)src)[lane];

    // norm
    float s = v.x * v.x + v.y * v.y + v.z * v.z + v.w * v.w;
    #pragma unroll
    for (int o = 16; o; o >>= 1) s += __shfl_xor_sync(0xffffffffu, s, o);
    if (lane == 0) {
        if (isB) g_n2[row] = s;
        else     g_n1[row] = s;
    }

    // split
    __half hx = __float2half_rn(v.x), hy = __float2half_rn(v.y);
    __half hz = __float2half_rn(v.z), hw = __float2half_rn(v.w);
    __half2 h01 = __halves2half2(hx, hy);
    __half2 h23 = __halves2half2(hz, hw);
    __half2 l01 = __halves2half2(__float2half_rn(v.x - __half2float(hx)),
                                 __float2half_rn(v.y - __half2float(hy)));
    __half2 l23 = __halves2half2(__float2half_rn(v.z - __half2float(hz)),
                                 __float2half_rn(v.w - __half2float(hw)));
    uint2 hp = make_uint2(*(uint32_t*)&h01, *(uint32_t*)&h23);
    uint2 lp = make_uint2(*(uint32_t*)&l01, *(uint32_t*)&l23);
    size_t j = (size_t)row * 32 + lane;
    ((uint2*)(isB ? g_Bh : g_Ah))[j] = hp;
    ((uint2*)(isB ? g_Bl : g_Al))[j] = lp;
}

// ---------------------------------------------------------------------------
// smem loaders (SW128-swizzled K-major tiles, 16B granules via cp.async)
// A: [half][kchunk 2][128 rows][128B]   B stage: [half][kchunk 2][64 rows][128B]
// ---------------------------------------------------------------------------
__device__ __forceinline__ void load_a_panel(uint32_t dstbase, int row0, int tid) {
    #pragma unroll
    for (int g = 0; g < 16; g++) {
        int idx = g * 256 + tid;            // 4096 granules
        int half_ = idx >> 11;
        int rem   = idx & 2047;
        int chunk = rem >> 10;
        int rem2  = rem & 1023;
        int row   = rem2 >> 3;
        int gi    = rem2 & 7;
        const __half* src = (half_ ? g_Al : g_Ah) +
                            (size_t)(row0 + row) * ND + chunk * 64 + gi * 8;
        uint32_t dst = dstbase + half_ * 32768 + chunk * 16384 +
                       SW128(row * 128 + gi * 16);
        CP_ASYNC16(dst, src);
    }
}
__device__ __forceinline__ void load_b_stage(uint32_t dstbase, int col0, int tid) {
    #pragma unroll
    for (int g = 0; g < 8; g++) {
        int idx = g * 256 + tid;            // 2048 granules
        int half_ = idx >> 10;
        int rem   = idx & 1023;
        int chunk = rem >> 9;
        int rem2  = rem & 511;
        int row   = rem2 >> 3;
        int gi    = rem2 & 7;
        const __half* src = (half_ ? g_Bl : g_Bh) +
                            (size_t)(col0 + row) * ND + chunk * 64 + gi * 8;
        uint32_t dst = dstbase + half_ * 16384 + chunk * 8192 +
                       SW128(row * 128 + gi * 16);
        CP_ASYNC16(dst, src);
    }
}

// ---------------------------------------------------------------------------
// Kernel 1: mma.sync fp16x3 GEMM + fused argmin
// 256 threads = 8 warps (4 row x 2 col); warp tile 32x32.
// Fused k-loop: load Ah/Al/Bh/Bl fragments once, issue 24 MMAs per k-step.
// ---------------------------------------------------------------------------
__global__ void __launch_bounds__(256, 1)
match_kernel() {
    extern __shared__ char smem[];
    const uint32_t sbase = smem_u32(smem);
    const int tid  = threadIdx.x;
    const int lane = tid & 31;
    const int warp = tid >> 5;
    const int wrow = (warp >> 1) * 32;
    const int wcol = (warp & 1) * 32;
    const int rowBase = blockIdx.x * BM;
    const int split   = blockIdx.y;
    const int colBase = split * COLS_PER_CTA;

    // per-lane ldmatrix geometry
    const int a_rl   = lane & 15;
    const int a_koff = (lane >> 4) * 8;
    const int b_nl   = (lane & 7) + (lane >> 4) * 8;
    const int b_koff = ((lane >> 3) & 1) * 8;

    // ---- prologue: A panel + n2 + first two B stages ----
    load_a_panel(sbase + SMEM_A, rowBase, tid);
    if (tid < 128)
        CP_ASYNC16(sbase + SMEM_N2 + tid * 16, g_n2 + colBase + tid * 4);
    load_b_stage(sbase + SMEM_B + 0 * BSTAGE, colBase + 0 * BN, tid);
    CP_COMMIT();                                    // G0 = A + n2 + B0
    load_b_stage(sbase + SMEM_B + 1 * BSTAGE, colBase + 1 * BN, tid);
    CP_COMMIT();                                    // G1 = B1

    const float* n2s = (const float*)(smem + SMEM_N2);

    float best[4];
    int   bidx[4];
    #pragma unroll
    for (int s = 0; s < 4; s++) { best[s] = 3.4e38f; bidx[s] = 0; }

    for (int i = 0; i < TILES; i++) {
        CP_WAIT1();            // B(i) resident
        __syncthreads();       // stage (i-1)%3 fully consumed by all warps

        // ---- prefetch B(i+2) immediately (hides gmem under MMAs) ----
        if (i + 2 < TILES)
            load_b_stage(sbase + SMEM_B + ((i + 2) % 3) * BSTAGE,
                         colBase + (i + 2) * BN, tid);
        CP_COMMIT();

        const uint32_t abase = sbase + SMEM_A;
        const uint32_t bbase = sbase + SMEM_B + (i % 3) * BSTAGE;

        float acc[2][4][4];
        #pragma unroll
        for (int m = 0; m < 2; m++)
            #pragma unroll
            for (int n = 0; n < 4; n++)
                #pragma unroll
                for (int c = 0; c < 4; c++) acc[m][n][c] = 0.0f;

        #pragma unroll
        for (int ks = 0; ks < 8; ks++) {
            uint32_t aH[2][4], aL[2][4], bH[2][4], bL[2][4];
            #pragma unroll
            for (int m = 0; m < 2; m++) {
                int row = wrow + m * 16 + a_rl;
                int kb  = ks * 16 + a_koff;
                uint32_t addr = abase + (kb >> 6) * 16384 + row * 128 +
                                (((kb & 63) * 2) ^ ((row & 7) << 4));
                LDMATRIX_X4(aH[m][0], aH[m][1], aH[m][2], aH[m][3], addr);
                LDMATRIX_X4(aL[m][0], aL[m][1], aL[m][2], aL[m][3], addr + 32768);
            }
            #pragma unroll
            for (int pr = 0; pr < 2; pr++) {
                int nrow = wcol + pr * 16 + b_nl;
                int kb   = ks * 16 + b_koff;
                uint32_t addr = bbase + (kb >> 6) * 8192 + nrow * 128 +
                                (((kb & 63) * 2) ^ ((nrow & 7) << 4));
                LDMATRIX_X4(bH[pr][0], bH[pr][1], bH[pr][2], bH[pr][3], addr);
                LDMATRIX_X4(bL[pr][0], bL[pr][1], bL[pr][2], bL[pr][3], addr + 16384);
            }
            #pragma unroll
            for (int m = 0; m < 2; m++) {
                // Ah * Bh
                MMA16816(acc[m][0], aH[m], bH[0][0], bH[0][1]);
                MMA16816(acc[m][1], aH[m], bH[0][2], bH[0][3]);
                MMA16816(acc[m][2], aH[m], bH[1][0], bH[1][1]);
                MMA16816(acc[m][3], aH[m], bH[1][2], bH[1][3]);
                // Ah * Bl
                MMA16816(acc[m][0], aH[m], bL[0][0], bL[0][1]);
                MMA16816(acc[m][1], aH[m], bL[0][2], bL[0][3]);
                MMA16816(acc[m][2], aH[m], bL[1][0], bL[1][1]);
                MMA16816(acc[m][3], aH[m], bL[1][2], bL[1][3]);
                // Al * Bh
                MMA16816(acc[m][0], aL[m], bH[0][0], bH[0][1]);
                MMA16816(acc[m][1], aL[m], bH[0][2], bH[0][3]);
                MMA16816(acc[m][2], aL[m], bH[1][0], bH[1][1]);
                MMA16816(acc[m][3], aL[m], bH[1][2], bH[1][3]);
            }
        }

        // ---- fused argmin epilogue (n2 from smem) ----
        const int c0 = colBase + i * BN + wcol;
        const int cloc = i * BN + wcol;
        float n2v[8];
        #pragma unroll
        for (int n = 0; n < 4; n++) {
            n2v[n * 2]     = n2s[cloc + n * 8 + (lane & 3) * 2];
            n2v[n * 2 + 1] = n2s[cloc + n * 8 + (lane & 3) * 2 + 1];
        }
        #pragma unroll
        for (int m = 0; m < 2; m++)
            #pragma unroll
            for (int n = 0; n < 4; n++)
                #pragma unroll
                for (int c = 0; c < 4; c++) {
                    float v = n2v[n * 2 + (c & 1)] - 2.0f * acc[m][n][c];
                    int col = c0 + n * 8 + (lane & 3) * 2 + (c & 1);
                    int s = m * 2 + (c >> 1);
                    if (v < best[s]) { best[s] = v; bidx[s] = col; }
                }
    }

    // ---- reduction: quad lanes share rows -> shfl, then 2 col-warps via smem
    __syncthreads();
    float* red_v = (float*)smem;                 // 256 floats
    int*   red_i = (int*)(smem + 1024);          // 256 ints
    #pragma unroll
    for (int s = 0; s < 4; s++) {
        float bv = best[s];
        int   bi = bidx[s];
        #pragma unroll
        for (int off = 1; off <= 2; off <<= 1) {
            float ov = __shfl_xor_sync(0xffffffffu, bv, off);
            int   oi = __shfl_xor_sync(0xffffffffu, bi, off);
            if (ov < bv || (ov == bv && oi < bi)) { bv = ov; bi = oi; }
        }
        if ((lane & 3) == 0) {
            int row = wrow + (s >> 1) * 16 + (s & 1) * 8 + (lane >> 2);
            red_v[row * 2 + (warp & 1)] = bv;
            red_i[row * 2 + (warp & 1)] = bi;
        }
    }
    __syncthreads();
    if (tid < BM) {
        float bv = red_v[tid * 2];
        int   bi = red_i[tid * 2];
        float ov = red_v[tid * 2 + 1];
        int   oi = red_i[tid * 2 + 1];
        if (ov < bv || (ov == bv && oi < bi)) { bv = ov; bi = oi; }
        g_pval[(rowBase + tid) * SPLITC + split] = bv;
        g_pidx[(rowBase + tid) * SPLITC + split] = bi;
    }
}

// ---------------------------------------------------------------------------
// Kernel 2: reduce SPLITC partials per row (warp per row), add n1, sqrt, write
// ---------------------------------------------------------------------------
__global__ void final_kernel(float* __restrict__ out) {
    int warp = (blockIdx.x * blockDim.x + threadIdx.x) >> 5;
    int lane = threadIdx.x & 31;
    if (warp >= NB1) return;
    float bv = 3.4e38f;
    int   bi = 0x7fffffff;
    if (lane < SPLITC) {
        bv = g_pval[warp * SPLITC + lane];
        bi = g_pidx[warp * SPLITC + lane];
    }
    #pragma unroll
    for (int off = 8; off; off >>= 1) {
        float ov = __shfl_xor_sync(0xffffffffu, bv, off);
        int   oi = __shfl_xor_sync(0xffffffffu, bi, off);
        if (ov < bv || (ov == bv && oi < bi)) { bv = ov; bi = oi; }
    }
    if (lane == 0) {
        float dm = g_n1[warp] + bv;
        out[warp] = sqrtf(fmaxf(dm, 0.0f));
        out[NB1 + 2 * warp]     = (float)warp;
        out[NB1 + 2 * warp + 1] = (float)bi;
    }
}

// ---------------------------------------------------------------------------
extern "C" void kernel_launch(void* const* d_in, const int* in_sizes, int n_in,
                              void* d_out, int out_size) {
    const float* d1 = (const float*)d_in[0];
    const float* d2 = (const float*)d_in[1];
    float* out = (float*)d_out;

    cudaFuncSetAttribute(match_kernel,
                         cudaFuncAttributeMaxDynamicSharedMemorySize, SMEM_BYTES);

    prep_kernel<<<(NB1 + NB2) / 8, 256>>>(d1, d2);
    match_kernel<<<dim3(NB1 / BM, SPLITC), 256, SMEM_BYTES>>>();
    final_kernel<<<NB1 / 8, 256>>>(out);
}